// round 14
// baseline (speedup 1.0000x reference)
#include <cuda_runtime.h>
#include <cuda_fp16.h>
#include <math.h>
#include <stdint.h>

#define N     8192
#define D     128
#define TWON  16384
#define NTILE 128
#define NPAIR 8256             // NTILE*(NTILE+1)/2
#define CHUNK 4

#define DIAG_EXP2  7.38905609893065f
#define SQRT_SCALE 1.6986436f  // sqrt(2/ln2): acc = log2(exp arg)

// -------- persistent device scratch --------
__device__ uint8_t g_Hq[TWON * D];  // normalized rows, pre-scaled, e4m3
__device__ float g_pos[N];
__device__ float g_rowsum[TWON];
__device__ int   g_ctr;

// ============================================================
// helpers
// ============================================================
__device__ __forceinline__ uint32_t smem_u32(const void* p) {
    uint32_t a;
    asm("{ .reg .u64 t; cvta.to.shared.u64 t, %1; cvt.u32.u64 %0, t; }" : "=r"(a) : "l"(p));
    return a;
}
__device__ __forceinline__ void cp_async16(uint32_t saddr, const void* gaddr) {
    asm volatile("cp.async.cg.shared.global [%0], [%1], 16;" :: "r"(saddr), "l"(gaddr) : "memory");
}
#define CP_COMMIT() asm volatile("cp.async.commit_group;" ::: "memory")
#define CP_WAIT0()  asm volatile("cp.async.wait_group 0;" ::: "memory")

__device__ __forceinline__ void ldmatrix_x4(uint32_t& r0, uint32_t& r1, uint32_t& r2,
                                            uint32_t& r3, uint32_t addr) {
    asm volatile("ldmatrix.sync.aligned.m8n8.x4.shared.b16 {%0,%1,%2,%3}, [%4];"
                 : "=r"(r0), "=r"(r1), "=r"(r2), "=r"(r3) : "r"(addr));
}
// e4m3 x e4m3 -> f32 accumulate, k=32
__device__ __forceinline__ void mma_fp8(float* c, const uint32_t* a, uint32_t b0, uint32_t b1) {
    asm volatile("mma.sync.aligned.m16n8k32.row.col.f32.e4m3.e4m3.f32 "
                 "{%0,%1,%2,%3}, {%4,%5,%6,%7}, {%8,%9}, {%0,%1,%2,%3};"
                 : "+f"(c[0]), "+f"(c[1]), "+f"(c[2]), "+f"(c[3])
                 : "r"(a[0]), "r"(a[1]), "r"(a[2]), "r"(a[3]), "r"(b0), "r"(b1));
}
__device__ __forceinline__ uint32_t f16x2_pack(float lo, float hi) {
    uint32_t r;  // cvt.rn.f16x2.f32 d,a,b : high=a, low=b
    asm("cvt.rn.f16x2.f32 %0, %1, %2;" : "=r"(r) : "f"(hi), "f"(lo));
    return r;
}
__device__ __forceinline__ uint32_t ex2_f16x2(uint32_t x) {
    uint32_t y;
    asm("ex2.approx.f16x2 %0, %1;" : "=r"(y) : "r"(x));
    return y;
}
__device__ __forceinline__ uint32_t hadd2(uint32_t a, uint32_t b) {
    uint32_t r;
    asm("add.rn.f16x2 %0, %1, %2;" : "=r"(r) : "r"(a), "r"(b));
    return r;
}
// pack 4 floats -> 4 e4m3 bytes (low to high)
__device__ __forceinline__ uint32_t e4m3_pack4(float x0, float x1, float x2, float x3) {
    uint16_t lo, hi;
    asm("cvt.rn.satfinite.e4m3x2.f32 %0, %1, %2;" : "=h"(lo) : "f"(x1), "f"(x0));
    asm("cvt.rn.satfinite.e4m3x2.f32 %0, %1, %2;" : "=h"(hi) : "f"(x3), "f"(x2));
    return (uint32_t)lo | ((uint32_t)hi << 16);
}
// t in [0, NPAIR) -> (I,J), I<=J, row-major over upper triangle
__device__ __forceinline__ void decode_pair(int t, int& I, int& J) {
    int r = NPAIR - t;
    float nf = (sqrtf(8.0f * (float)r + 1.0f) - 1.0f) * 0.5f;
    int n = (int)ceilf(nf);
    while (n * (n + 1) / 2 < r) n++;
    while (n >= 1 && (n - 1) * n / 2 >= r) n--;
    I = NTILE - n;
    int S = NPAIR - n * (n + 1) / 2;
    J = I + (t - S);
}

// ============================================================
// Kernel A: normalize + pre-scale to e4m3; zero rowsum/ctr
// ============================================================
__global__ void nt_norm_kernel(const float* __restrict__ h1,
                               const float* __restrict__ h2) {
    int gid = blockIdx.x * blockDim.x + threadIdx.x;
    if (gid < TWON) g_rowsum[gid] = 0.0f;
    if (gid == 0)   g_ctr = 0;

    int warp = gid >> 5;
    int lane = threadIdx.x & 31;
    if (warp >= N) return;

    float4 a = ((const float4*)(h1 + (size_t)warp * D))[lane];
    float4 b = ((const float4*)(h2 + (size_t)warp * D))[lane];

    float sa = a.x*a.x + a.y*a.y + a.z*a.z + a.w*a.w;
    float sb = b.x*b.x + b.y*b.y + b.z*b.z + b.w*b.w;
    float sd = a.x*b.x + a.y*b.y + a.z*b.z + a.w*b.w;
    #pragma unroll
    for (int o = 16; o; o >>= 1) {
        sa += __shfl_xor_sync(0xffffffffu, sa, o);
        sb += __shfl_xor_sync(0xffffffffu, sb, o);
        sd += __shfl_xor_sync(0xffffffffu, sd, o);
    }
    float ra = 1.0f / fmaxf(sqrtf(sa), 1e-12f);
    float rb = 1.0f / fmaxf(sqrtf(sb), 1e-12f);
    if (lane == 0) g_pos[warp] = sd * ra * rb;

    float fa = ra * SQRT_SCALE, fb = rb * SQRT_SCALE;
    uint32_t pa = e4m3_pack4(a.x*fa, a.y*fa, a.z*fa, a.w*fa);
    uint32_t pb = e4m3_pack4(b.x*fb, b.y*fb, b.z*fb, b.w*fb);
    ((uint32_t*)(g_Hq + (size_t)warp * D))[lane]       = pa;
    ((uint32_t*)(g_Hq + (size_t)(warp + N) * D))[lane] = pb;
}

// ============================================================
// Kernel B: symmetric persistent GEMM — occ 2, FP8 e4m3 MMA.
//   m16n8k32: 4 k-steps (half the HMMA instruction count).
// ============================================================
#define ROWB      144                    // 128 fp8 + 16 pad
#define T_BYTES   (128 * ROWB)           // 18432
#define A_OFF     0
#define B0_OFF    T_BYTES
#define B1_OFF    (2 * T_BYTES)
#define SMEM_SZ   (3 * T_BYTES)          // 55296
#define NT        256

__device__ __forceinline__ void cp_tile(uint32_t buf, int blk, int tid) {
    const uint8_t* src = g_Hq + (size_t)blk * 128 * D;
    #pragma unroll
    for (int c = tid; c < 1024; c += NT) {
        int r = c >> 3, kc = c & 7;
        cp_async16(buf + r * ROWB + kc * 16, src + (size_t)r * D + kc * 16);
    }
}

__global__ void __launch_bounds__(NT, 2) nt_gemm_sym() {
    extern __shared__ char smem[];
    __shared__ int s_c;
    uint32_t sb = smem_u32(smem);
    const int tid    = threadIdx.x;
    const int lane   = tid & 31;
    const int wid    = tid >> 5;
    const int warp_m = wid & 3;      // rows warp_m*32
    const int warp_n = wid >> 2;     // cols warp_n*64

    // ---- first chunk + first tile load ----
    if (tid == 0) s_c = atomicAdd(&g_ctr, 1);
    __syncthreads();
    int cpos = s_c * CHUNK;
    int cend = cpos + CHUNK;
    if (cpos >= NPAIR) { cpos = NPAIR; cend = NPAIR; }

    int curT = (cpos < cend) ? cpos++ : NPAIR;
    int curI = 0, curJ = 0;
    if (curT < NPAIR) {
        decode_pair(curT, curI, curJ);
        cp_tile(sb + A_OFF, curI, tid);
        cp_tile(sb + B0_OFF, curJ, tid);
    }
    CP_COMMIT();

    int p = 0, prevI = -1;
    uint32_t afrag[4][2][4];   // 4 k-steps x 2 m-atoms x 4 regs
    float rs[4] = {0.f, 0.f, 0.f, 0.f};

    while (curT < NPAIR) {
        // ---- acquire next index; wait cur data; one block sync ----
        bool need = (cpos >= cend);
        if (need && tid == 0) s_c = atomicAdd(&g_ctr, 1);
        CP_WAIT0();
        __syncthreads();
        if (need) {
            cpos = s_c * CHUNK;
            if (cpos > NPAIR) cpos = NPAIR;
            cend = cpos + CHUNK;
            if (cend > NPAIR) cend = NPAIR;
        }
        int nxtT = (cpos < cend) ? cpos++ : NPAIR;
        int nxtI = 0, nxtJ = 0;
        if (nxtT < NPAIR) decode_pair(nxtT, nxtI, nxtJ);

        // ---- I changed: flush deferred row sums, (re)load A fragments ----
        if (curI != prevI) {
            if (prevI >= 0) {
                #pragma unroll
                for (int i = 0; i < 4; ++i) {
                    rs[i] += __shfl_xor_sync(0xffffffffu, rs[i], 1);
                    rs[i] += __shfl_xor_sync(0xffffffffu, rs[i], 2);
                }
                if ((lane & 3) == 0) {
                    int r8 = lane >> 2;
                    #pragma unroll
                    for (int i = 0; i < 4; ++i)
                        atomicAdd(&g_rowsum[prevI * 128 + warp_m * 32 + i * 8 + r8], rs[i]);
                }
                rs[0] = rs[1] = rs[2] = rs[3] = 0.f;
            }
            uint32_t abase = sb + A_OFF + (warp_m * 32 + (lane & 15)) * ROWB + (lane >> 4) * 16;
            #pragma unroll
            for (int kst = 0; kst < 4; ++kst)
                #pragma unroll
                for (int ma = 0; ma < 2; ++ma)
                    ldmatrix_x4(afrag[kst][ma][0], afrag[kst][ma][1],
                                afrag[kst][ma][2], afrag[kst][ma][3],
                                abase + ma * 16 * ROWB + kst * 32);
            prevI = curI;
        }

        // ---- prefetch next tile (A-buf reusable: afrag lives in regs) ----
        if (nxtT < NPAIR) {
            if (nxtI != curI) {
                __syncthreads();   // all warps' afrag LDSM done before A overwrite
                cp_tile(sb + A_OFF, nxtI, tid);
            }
            cp_tile(sb + ((p ^ 1) ? B1_OFF : B0_OFF), nxtJ, tid);
        }
        CP_COMMIT();

        // ---- compute cur from B buffer p ----
        const bool diag = (curI == curJ);
        uint32_t colacc[8];
        #pragma unroll
        for (int na = 0; na < 8; ++na) colacc[na] = 0;
        uint32_t rlo[2] = {0, 0}, rhi[2] = {0, 0};

        uint32_t bbase = sb + (p ? B1_OFF : B0_OFF)
                       + (warp_n * 64 + (lane & 15)) * ROWB + (lane >> 4) * 16;

        #pragma unroll
        for (int pr = 0; pr < 4; ++pr) {   // n-strip: 16 j-rows
            float acc[2][2][4];
            #pragma unroll
            for (int ma = 0; ma < 2; ++ma)
                #pragma unroll
                for (int nl = 0; nl < 2; ++nl)
                    #pragma unroll
                    for (int q = 0; q < 4; ++q) acc[ma][nl][q] = 0.f;

            uint32_t bq[2][4];
            ldmatrix_x4(bq[0][0], bq[0][1], bq[0][2], bq[0][3],
                        bbase + pr * 16 * ROWB);
            #pragma unroll
            for (int kst = 0; kst < 4; ++kst) {
                int cb = kst & 1, nb = cb ^ 1;
                if (kst < 3)
                    ldmatrix_x4(bq[nb][0], bq[nb][1], bq[nb][2], bq[nb][3],
                                bbase + pr * 16 * ROWB + (kst + 1) * 32);
                mma_fp8(acc[0][0], afrag[kst][0], bq[cb][0], bq[cb][2]);
                mma_fp8(acc[0][1], afrag[kst][0], bq[cb][1], bq[cb][3]);
                mma_fp8(acc[1][0], afrag[kst][1], bq[cb][0], bq[cb][2]);
                mma_fp8(acc[1][1], afrag[kst][1], bq[cb][1], bq[cb][3]);
            }
            // epilogue: pack f32 pairs -> f16x2, exp2, accumulate
            #pragma unroll
            for (int ma = 0; ma < 2; ++ma)
                #pragma unroll
                for (int nl = 0; nl < 2; ++nl) {
                    uint32_t e01 = ex2_f16x2(f16x2_pack(acc[ma][nl][0], acc[ma][nl][1]));
                    uint32_t e23 = ex2_f16x2(f16x2_pack(acc[ma][nl][2], acc[ma][nl][3]));
                    rlo[ma] = hadd2(rlo[ma], e01);
                    rhi[ma] = hadd2(rhi[ma], e23);
                    colacc[pr * 2 + nl] = hadd2(colacc[pr * 2 + nl], hadd2(e01, e23));
                }
        }

        // fold tile row partials into persistent f32 accumulators
        #pragma unroll
        for (int ma = 0; ma < 2; ++ma) {
            float2 glo = __half22float2(*(__half2*)&rlo[ma]);
            float2 ghi = __half22float2(*(__half2*)&rhi[ma]);
            rs[ma*2]     += glo.x + glo.y;
            rs[ma*2 + 1] += ghi.x + ghi.y;
        }

        // ---- colsum flush (per tile; symmetry) ----
        if (!diag) {
            #pragma unroll
            for (int na = 0; na < 8; ++na) {
                uint32_t v = colacc[na];
                v = hadd2(v, __shfl_xor_sync(0xffffffffu, v, 4));
                v = hadd2(v, __shfl_xor_sync(0xffffffffu, v, 8));
                v = hadd2(v, __shfl_xor_sync(0xffffffffu, v, 16));
                if (lane < 4) {
                    float2 cs = __half22float2(*(__half2*)&v);
                    int col = curJ * 128 + warp_n * 64 + na * 8 + lane * 2;
                    atomicAdd(&g_rowsum[col],     cs.x);
                    atomicAdd(&g_rowsum[col + 1], cs.y);
                }
            }
        }

        // ---- rotate ----
        curT = nxtT; curI = nxtI; curJ = nxtJ;
        p ^= 1;
    }

    // ---- final deferred row flush ----
    if (prevI >= 0) {
        #pragma unroll
        for (int i = 0; i < 4; ++i) {
            rs[i] += __shfl_xor_sync(0xffffffffu, rs[i], 1);
            rs[i] += __shfl_xor_sync(0xffffffffu, rs[i], 2);
        }
        if ((lane & 3) == 0) {
            int r8 = lane >> 2;
            #pragma unroll
            for (int i = 0; i < 4; ++i)
                atomicAdd(&g_rowsum[prevI * 128 + warp_m * 32 + i * 8 + r8], rs[i]);
        }
    }
}

// ============================================================
// Kernel C: loss = mean( log(rowsum - exp(2)) - 2*pos )
// ============================================================
__global__ void nt_loss_kernel(float* __restrict__ out) {
    __shared__ double sred[32];
    const int tid  = threadIdx.x;   // 1024
    const int lane = tid & 31;
    const int wid  = tid >> 5;

    double s = 0.0;
    for (int i = tid; i < TWON; i += 1024) {
        float denom = g_rowsum[i] - DIAG_EXP2;
        float term  = logf(denom) - 2.0f * g_pos[i & (N - 1)];
        s += (double)term;
    }
    #pragma unroll
    for (int o = 16; o; o >>= 1) s += __shfl_xor_sync(0xffffffffu, s, o);
    if (lane == 0) sred[wid] = s;
    __syncthreads();
    if (wid == 0) {
        double tt = sred[lane];
        #pragma unroll
        for (int o = 16; o; o >>= 1) tt += __shfl_xor_sync(0xffffffffu, tt, o);
        if (lane == 0) out[0] = (float)(tt / (double)TWON);
    }
}

// ============================================================
extern "C" void kernel_launch(void* const* d_in, const int* in_sizes, int n_in,
                              void* d_out, int out_size) {
    const float* h1 = (const float*)d_in[0];
    const float* h2 = (const float*)d_in[1];
    float* out = (float*)d_out;

    nt_norm_kernel<<<1024, 256>>>(h1, h2);

    cudaFuncSetAttribute(nt_gemm_sym,
                         cudaFuncAttributeMaxDynamicSharedMemorySize, SMEM_SZ);
    nt_gemm_sym<<<296, NT, SMEM_SZ>>>();

    nt_loss_kernel<<<1, 1024>>>(out);
}